// round 1
// baseline (speedup 1.0000x reference)
#include <cuda_runtime.h>

// ---------------------------------------------------------------------------
// SelfAttention: x[2,4096,512] -> QKV proj -> 8-head attn (d=64) -> out proj
// Round 0: fp32 baseline. 3 kernels: SGEMM(qkv) -> flash-attn -> SGEMM(out).
// ---------------------------------------------------------------------------

#define DIMX   512
#define INNER  512
#define NHEAD  8
#define HSIZE  64
#define BATCH  2
#define SEQ    4096
#define MTOT   (BATCH * SEQ)      // 8192
#define QKVN   (3 * INNER)        // 1536

// Scratch (device globals: no allocation allowed anywhere)
__device__ float g_qkv[(size_t)MTOT * QKVN];   // [8192, 1536]
__device__ float g_attn[(size_t)MTOT * INNER]; // [8192, 512]

// ---------------------------------------------------------------------------
// Tiled SGEMM with bias: C[M,N] = A[M,K] @ B[K,N] + bias[N]
// BM=128 BN=64 BK=16, 256 threads, 8x4 per-thread micro-tile.
// M % 128 == 0, N % 64 == 0, K % 16 == 0 (holds for all our shapes).
// ---------------------------------------------------------------------------
__global__ __launch_bounds__(256)
void sgemm_bias_kernel(const float* __restrict__ A, const float* __restrict__ Bm,
                       const float* __restrict__ bias, float* __restrict__ C,
                       int M, int N, int K)
{
    constexpr int BM = 128, BN = 64, BK = 16, TM = 8, TN = 4;
    __shared__ float As[BK][BM];       // stored transposed: As[k][m]
    __shared__ float Bs[BK][BN];

    const int tid = threadIdx.x;
    const int tx  = tid & 15;          // 0..15 (col group)
    const int ty  = tid >> 4;          // 0..15 (row group)
    const int m0  = blockIdx.y * BM;
    const int n0  = blockIdx.x * BN;

    float acc[TM][TN];
#pragma unroll
    for (int i = 0; i < TM; ++i)
#pragma unroll
        for (int j = 0; j < TN; ++j) acc[i][j] = 0.f;

    for (int k0 = 0; k0 < K; k0 += BK) {
        // --- load A tile 128x16 (512 float4, 2 per thread), transpose to As[k][m]
#pragma unroll
        for (int it = 0; it < 2; ++it) {
            int l  = tid + it * 256;        // 0..511
            int r  = l >> 2;                // row in tile 0..127
            int c4 = l & 3;                 // which float4 of the 16-float row
            float4 a = *(const float4*)(A + (size_t)(m0 + r) * K + k0 + c4 * 4);
            As[c4 * 4 + 0][r] = a.x;
            As[c4 * 4 + 1][r] = a.y;
            As[c4 * 4 + 2][r] = a.z;
            As[c4 * 4 + 3][r] = a.w;
        }
        // --- load B tile 16x64 (256 float4, 1 per thread)
        {
            int r  = tid >> 4;              // 0..15
            int c4 = tid & 15;              // 0..15
            float4 b = *(const float4*)(Bm + (size_t)(k0 + r) * N + n0 + c4 * 4);
            *(float4*)&Bs[r][c4 * 4] = b;
        }
        __syncthreads();

#pragma unroll
        for (int kk = 0; kk < BK; ++kk) {
            float4 a0 = *(const float4*)&As[kk][ty * TM + 0];
            float4 a1 = *(const float4*)&As[kk][ty * TM + 4];
            float4 b0 = *(const float4*)&Bs[kk][tx * TN];
            float a[TM] = {a0.x, a0.y, a0.z, a0.w, a1.x, a1.y, a1.z, a1.w};
            float b[TN] = {b0.x, b0.y, b0.z, b0.w};
#pragma unroll
            for (int i = 0; i < TM; ++i)
#pragma unroll
                for (int j = 0; j < TN; ++j)
                    acc[i][j] = fmaf(a[i], b[j], acc[i][j]);
        }
        __syncthreads();
    }

    // --- epilogue: add bias, vectorized store
    const int nc = n0 + tx * TN;
    float4 bb = *(const float4*)(bias + nc);
#pragma unroll
    for (int i = 0; i < TM; ++i) {
        int m = m0 + ty * TM + i;
        float4 o;
        o.x = acc[i][0] + bb.x;
        o.y = acc[i][1] + bb.y;
        o.z = acc[i][2] + bb.z;
        o.w = acc[i][3] + bb.w;
        *(float4*)(C + (size_t)m * N + nc) = o;
    }
}

// ---------------------------------------------------------------------------
// Flash attention, fp32. One thread owns one query row (q[64], o[64] in regs).
// Block = 256 threads = 256 query rows for one (b, h). K/V tiles of 32 keys
// staged in smem; all compute reads are warp-broadcast LDS.128 (conflict-free).
// ---------------------------------------------------------------------------
#define AROWS 256
#define TKEYS 32

__global__ __launch_bounds__(256)
void flash_attn_kernel(const float* __restrict__ qkv, float* __restrict__ attn)
{
    __shared__ float4 Ks[TKEYS * 16];   // 32 keys x 64 floats
    __shared__ float4 Vs[TKEYS * 16];

    const int t = threadIdx.x;
    const int h = blockIdx.y;
    const int b = blockIdx.z;
    const int n = blockIdx.x * AROWS + t;

    const size_t rowbase = (size_t)(b * SEQ + n) * QKVN + h * HSIZE;

    // q row, pre-scaled by 1/sqrt(64) = 0.125
    float4 q4[16];
#pragma unroll
    for (int d = 0; d < 16; ++d) {
        float4 v = ((const float4*)(qkv + rowbase))[d];
        q4[d] = make_float4(v.x * 0.125f, v.y * 0.125f, v.z * 0.125f, v.w * 0.125f);
    }
    float4 o4[16];
#pragma unroll
    for (int d = 0; d < 16; ++d) o4[d] = make_float4(0.f, 0.f, 0.f, 0.f);
    float mrun = -1e30f, lrun = 0.f;

    for (int m0 = 0; m0 < SEQ; m0 += TKEYS) {
        __syncthreads();   // previous tile's compute done before overwrite
        // load K,V tile: 512 float4 each, 2 per thread
#pragma unroll
        for (int it = 0; it < 2; ++it) {
            int idx = t + it * 256;                 // 0..511
            int r = idx >> 4, c = idx & 15;
            size_t grow = (size_t)(b * SEQ + m0 + r) * QKVN + h * HSIZE;
            Ks[idx] = ((const float4*)(qkv + grow + INNER))[c];
            Vs[idx] = ((const float4*)(qkv + grow + 2 * INNER))[c];
        }
        __syncthreads();

        // scores s[j] = (q/8) . K[j]
        float s[TKEYS];
#pragma unroll 4
        for (int j = 0; j < TKEYS; ++j) {
            float acc = 0.f;
#pragma unroll
            for (int d = 0; d < 16; ++d) {
                float4 kk = Ks[j * 16 + d];
                acc = fmaf(q4[d].x, kk.x, acc);
                acc = fmaf(q4[d].y, kk.y, acc);
                acc = fmaf(q4[d].z, kk.z, acc);
                acc = fmaf(q4[d].w, kk.w, acc);
            }
            s[j] = acc;
        }

        // online softmax update
        float mt = s[0];
#pragma unroll
        for (int j = 1; j < TKEYS; ++j) mt = fmaxf(mt, s[j]);
        float mnew = fmaxf(mrun, mt);
        float corr = __expf(mrun - mnew);
        mrun = mnew;
        lrun *= corr;
#pragma unroll
        for (int d = 0; d < 16; ++d) {
            o4[d].x *= corr; o4[d].y *= corr; o4[d].z *= corr; o4[d].w *= corr;
        }
#pragma unroll
        for (int j = 0; j < TKEYS; ++j) {
            float p = __expf(s[j] - mnew);
            s[j] = p;
            lrun += p;
        }

        // o += p @ V
#pragma unroll 4
        for (int j = 0; j < TKEYS; ++j) {
            float p = s[j];
#pragma unroll
            for (int d = 0; d < 16; ++d) {
                float4 vv = Vs[j * 16 + d];
                o4[d].x = fmaf(p, vv.x, o4[d].x);
                o4[d].y = fmaf(p, vv.y, o4[d].y);
                o4[d].z = fmaf(p, vv.z, o4[d].z);
                o4[d].w = fmaf(p, vv.w, o4[d].w);
            }
        }
    }

    const float inv = 1.f / lrun;
    float* orow = attn + (size_t)(b * SEQ + n) * INNER + h * HSIZE;
#pragma unroll
    for (int d = 0; d < 16; ++d) {
        float4 o;
        o.x = o4[d].x * inv; o.y = o4[d].y * inv;
        o.z = o4[d].z * inv; o.w = o4[d].w * inv;
        ((float4*)orow)[d] = o;
    }
}

// ---------------------------------------------------------------------------
// Launch
// ---------------------------------------------------------------------------
extern "C" void kernel_launch(void* const* d_in, const int* in_sizes, int n_in,
                              void* d_out, int out_size)
{
    const float* x     = (const float*)d_in[0];
    const float* w_qkv = (const float*)d_in[1];
    const float* b_qkv = (const float*)d_in[2];
    const float* w_out = (const float*)d_in[3];
    const float* b_out = (const float*)d_in[4];
    float* out = (float*)d_out;

    float *qkv_ptr, *attn_ptr;
    cudaGetSymbolAddress((void**)&qkv_ptr, g_qkv);
    cudaGetSymbolAddress((void**)&attn_ptr, g_attn);

    // 1) qkv = x @ w_qkv + b_qkv          [8192,1536]
    {
        dim3 grid(QKVN / 64, MTOT / 128);
        sgemm_bias_kernel<<<grid, 256>>>(x, w_qkv, b_qkv, qkv_ptr, MTOT, QKVN, DIMX);
    }
    // 2) flash attention -> g_attn        [8192,512]
    {
        dim3 grid(SEQ / AROWS, NHEAD, BATCH);
        flash_attn_kernel<<<grid, 256>>>(qkv_ptr, attn_ptr);
    }
    // 3) out = attn @ w_out + b_out       [8192,512]
    {
        dim3 grid(DIMX / 64, MTOT / 128);
        sgemm_bias_kernel<<<grid, 256>>>(attn_ptr, w_out, b_out, out, MTOT, DIMX, INNER);
    }
}

// round 2
// speedup vs baseline: 2.8540x; 2.8540x over previous
#include <cuda_runtime.h>
#include <cstdint>

// ---------------------------------------------------------------------------
// SelfAttention: x[2,4096,512] -> QKV proj -> 8-head attn (d=64) -> out proj
// Round 1: tf32 mma flash-attention. SGEMMs still fp32 SIMT (convert next).
// ---------------------------------------------------------------------------

#define DIMX   512
#define INNER  512
#define NHEAD  8
#define HSIZE  64
#define BATCH  2
#define SEQ    4096
#define MTOT   (BATCH * SEQ)      // 8192
#define QKVN   (3 * INNER)        // 1536

// Scratch (device globals: no allocation allowed anywhere)
__device__ float g_qkv[(size_t)MTOT * QKVN];   // [8192, 1536]
__device__ float g_attn[(size_t)MTOT * INNER]; // [8192, 512]

// ---------------------------------------------------------------------------
// Tiled SGEMM with bias: C[M,N] = A[M,K] @ B[K,N] + bias[N]  (unchanged)
// ---------------------------------------------------------------------------
__global__ __launch_bounds__(256)
void sgemm_bias_kernel(const float* __restrict__ A, const float* __restrict__ Bm,
                       const float* __restrict__ bias, float* __restrict__ C,
                       int M, int N, int K)
{
    constexpr int BM = 128, BN = 64, BK = 16, TM = 8, TN = 4;
    __shared__ float As[BK][BM];
    __shared__ float Bs[BK][BN];

    const int tid = threadIdx.x;
    const int tx  = tid & 15;
    const int ty  = tid >> 4;
    const int m0  = blockIdx.y * BM;
    const int n0  = blockIdx.x * BN;

    float acc[TM][TN];
#pragma unroll
    for (int i = 0; i < TM; ++i)
#pragma unroll
        for (int j = 0; j < TN; ++j) acc[i][j] = 0.f;

    for (int k0 = 0; k0 < K; k0 += BK) {
#pragma unroll
        for (int it = 0; it < 2; ++it) {
            int l  = tid + it * 256;
            int r  = l >> 2;
            int c4 = l & 3;
            float4 a = *(const float4*)(A + (size_t)(m0 + r) * K + k0 + c4 * 4);
            As[c4 * 4 + 0][r] = a.x;
            As[c4 * 4 + 1][r] = a.y;
            As[c4 * 4 + 2][r] = a.z;
            As[c4 * 4 + 3][r] = a.w;
        }
        {
            int r  = tid >> 4;
            int c4 = tid & 15;
            float4 b = *(const float4*)(Bm + (size_t)(k0 + r) * N + n0 + c4 * 4);
            *(float4*)&Bs[r][c4 * 4] = b;
        }
        __syncthreads();

#pragma unroll
        for (int kk = 0; kk < BK; ++kk) {
            float4 a0 = *(const float4*)&As[kk][ty * TM + 0];
            float4 a1 = *(const float4*)&As[kk][ty * TM + 4];
            float4 b0 = *(const float4*)&Bs[kk][tx * TN];
            float a[TM] = {a0.x, a0.y, a0.z, a0.w, a1.x, a1.y, a1.z, a1.w};
            float b[TN] = {b0.x, b0.y, b0.z, b0.w};
#pragma unroll
            for (int i = 0; i < TM; ++i)
#pragma unroll
                for (int j = 0; j < TN; ++j)
                    acc[i][j] = fmaf(a[i], b[j], acc[i][j]);
        }
        __syncthreads();
    }

    const int nc = n0 + tx * TN;
    float4 bb = *(const float4*)(bias + nc);
#pragma unroll
    for (int i = 0; i < TM; ++i) {
        int m = m0 + ty * TM + i;
        float4 o;
        o.x = acc[i][0] + bb.x;
        o.y = acc[i][1] + bb.y;
        o.z = acc[i][2] + bb.z;
        o.w = acc[i][3] + bb.w;
        *(float4*)(C + (size_t)m * N + nc) = o;
    }
}

// ---------------------------------------------------------------------------
// tf32 helpers
// ---------------------------------------------------------------------------
__device__ __forceinline__ uint32_t f2tf32(float f) {
    uint32_t r;
    asm("cvt.rna.tf32.f32 %0, %1;" : "=r"(r) : "f"(f));
    return r;
}

__device__ __forceinline__ void mma_tf32(float* d, const uint32_t* a,
                                         uint32_t b0, uint32_t b1)
{
    asm volatile(
        "mma.sync.aligned.m16n8k8.row.col.f32.tf32.tf32.f32 "
        "{%0,%1,%2,%3}, {%4,%5,%6,%7}, {%8,%9}, {%0,%1,%2,%3};\n"
        : "+f"(d[0]), "+f"(d[1]), "+f"(d[2]), "+f"(d[3])
        : "r"(a[0]), "r"(a[1]), "r"(a[2]), "r"(a[3]), "r"(b0), "r"(b1));
}

// ---------------------------------------------------------------------------
// Flash attention with tf32 mma.
// Block = 128 threads (4 warps) = 64 query rows for one (b, h).
// Warp w owns query rows [w*16, w*16+16). Key/Value tiles of 64 staged in smem.
//
// m16n8k8 fragment layouts (lane = 4*qr + qc, qr=lane/4, qc=lane%4):
//   A(16x8):  a0=(qr,   qc) a1=(qr+8, qc) a2=(qr,   qc+4) a3=(qr+8, qc+4)
//   B(8x8):   b0=(qc,   qr) b1=(qc+4, qr)          [row=k, col=n]
//   C(16x8):  c0=(qr, 2qc) c1=(qr, 2qc+1) c2=(qr+8, 2qc) c3=(qr+8, 2qc+1)
// ---------------------------------------------------------------------------
#define MQ   64
#define TKEY 64
#define STQ  68   // stride (floats) for Qs/Ks/Ps: (4*row + col) % 32 distinct
#define STV  72   // stride for Vs: (8*qc + qr) % 32 distinct for PV B-frags

#define QS_OFF 0
#define KS_OFF (MQ * STQ)                   // 4352
#define VS_OFF (KS_OFF + TKEY * STQ)        // 8704
#define PS_OFF (VS_OFF + TKEY * STV)        // 13312
#define SMEM_U32 (PS_OFF + 4 * 16 * STQ)    // 17664
#define SMEM_BYTES (SMEM_U32 * 4)           // 70656

__global__ __launch_bounds__(128)
void flash_mma_kernel(const float* __restrict__ qkv, float* __restrict__ attn)
{
    extern __shared__ uint32_t sm[];
    uint32_t* Qs = sm + QS_OFF;
    uint32_t* Ks = sm + KS_OFF;
    uint32_t* Vs = sm + VS_OFF;

    const int t    = threadIdx.x;
    const int warp = t >> 5;
    const int lane = t & 31;
    const int qr   = lane >> 2;   // 0..7
    const int qc   = lane & 3;    // 0..3
    const int h    = blockIdx.y;
    const int b    = blockIdx.z;
    const int q0   = blockIdx.x * MQ;

    uint32_t* Pw = sm + PS_OFF + warp * (16 * STQ);

    // ---- load Q tile (64x64), scale by 1/8, convert tf32 ----
#pragma unroll
    for (int it = 0; it < 8; ++it) {
        int idx = t + it * 128;            // 0..1023 float4 slots
        int r = idx >> 4, c4 = idx & 15;
        float4 v = *(const float4*)(qkv + (size_t)(b * SEQ + q0 + r) * QKVN
                                        + h * HSIZE + c4 * 4);
        uint4 u = make_uint4(f2tf32(v.x * 0.125f), f2tf32(v.y * 0.125f),
                             f2tf32(v.z * 0.125f), f2tf32(v.w * 0.125f));
        *(uint4*)&Qs[r * STQ + c4 * 4] = u;
    }
    __syncthreads();

    // ---- Q A-fragments: 8 k-tiles, held in registers for the whole kernel ----
    uint32_t aQ[8][4];
#pragma unroll
    for (int k0 = 0; k0 < 8; ++k0) {
        aQ[k0][0] = Qs[(warp * 16 + qr)     * STQ + k0 * 8 + qc];
        aQ[k0][1] = Qs[(warp * 16 + qr + 8) * STQ + k0 * 8 + qc];
        aQ[k0][2] = Qs[(warp * 16 + qr)     * STQ + k0 * 8 + qc + 4];
        aQ[k0][3] = Qs[(warp * 16 + qr + 8) * STQ + k0 * 8 + qc + 4];
    }

    float o[8][4];
#pragma unroll
    for (int n0 = 0; n0 < 8; ++n0)
#pragma unroll
        for (int j = 0; j < 4; ++j) o[n0][j] = 0.f;
    float mrow0 = -1e30f, mrow1 = -1e30f, lrow0 = 0.f, lrow1 = 0.f;

    for (int kt = 0; kt < SEQ; kt += TKEY) {
        __syncthreads();   // all warps done with previous Ks/Vs
        // ---- load K,V tile (64x64 each), convert tf32 ----
#pragma unroll
        for (int it = 0; it < 8; ++it) {
            int idx = t + it * 128;
            int r = idx >> 4, c4 = idx & 15;
            size_t base = (size_t)(b * SEQ + kt + r) * QKVN + h * HSIZE + c4 * 4;
            float4 kv = *(const float4*)(qkv + base + INNER);
            float4 vv = *(const float4*)(qkv + base + 2 * INNER);
            *(uint4*)&Ks[r * STQ + c4 * 4] =
                make_uint4(f2tf32(kv.x), f2tf32(kv.y), f2tf32(kv.z), f2tf32(kv.w));
            *(uint4*)&Vs[r * STV + c4 * 4] =
                make_uint4(f2tf32(vv.x), f2tf32(vv.y), f2tf32(vv.z), f2tf32(vv.w));
        }
        __syncthreads();

        // ---- S = Q @ K^T : 8 n-tiles of m16n8 ----
        float s[8][4];
#pragma unroll
        for (int n0 = 0; n0 < 8; ++n0) {
            s[n0][0] = s[n0][1] = s[n0][2] = s[n0][3] = 0.f;
#pragma unroll
            for (int k0 = 0; k0 < 8; ++k0) {
                uint32_t b0 = Ks[(n0 * 8 + qr) * STQ + k0 * 8 + qc];
                uint32_t b1 = Ks[(n0 * 8 + qr) * STQ + k0 * 8 + qc + 4];
                mma_tf32(s[n0], aQ[k0], b0, b1);
            }
        }

        // ---- online softmax (rows qr and qr+8 of this warp's 16) ----
        float mt0 = -1e30f, mt1 = -1e30f;
#pragma unroll
        for (int n0 = 0; n0 < 8; ++n0) {
            mt0 = fmaxf(mt0, fmaxf(s[n0][0], s[n0][1]));
            mt1 = fmaxf(mt1, fmaxf(s[n0][2], s[n0][3]));
        }
        mt0 = fmaxf(mt0, __shfl_xor_sync(0xffffffffu, mt0, 1));
        mt0 = fmaxf(mt0, __shfl_xor_sync(0xffffffffu, mt0, 2));
        mt1 = fmaxf(mt1, __shfl_xor_sync(0xffffffffu, mt1, 1));
        mt1 = fmaxf(mt1, __shfl_xor_sync(0xffffffffu, mt1, 2));

        float mn0 = fmaxf(mrow0, mt0), mn1 = fmaxf(mrow1, mt1);
        float cr0 = __expf(mrow0 - mn0), cr1 = __expf(mrow1 - mn1);
        mrow0 = mn0; mrow1 = mn1;

        float ls0 = 0.f, ls1 = 0.f;
#pragma unroll
        for (int n0 = 0; n0 < 8; ++n0) {
            s[n0][0] = __expf(s[n0][0] - mn0);
            s[n0][1] = __expf(s[n0][1] - mn0);
            s[n0][2] = __expf(s[n0][2] - mn1);
            s[n0][3] = __expf(s[n0][3] - mn1);
            ls0 += s[n0][0] + s[n0][1];
            ls1 += s[n0][2] + s[n0][3];
            o[n0][0] *= cr0; o[n0][1] *= cr0;
            o[n0][2] *= cr1; o[n0][3] *= cr1;
        }
        ls0 += __shfl_xor_sync(0xffffffffu, ls0, 1);
        ls0 += __shfl_xor_sync(0xffffffffu, ls0, 2);
        ls1 += __shfl_xor_sync(0xffffffffu, ls1, 1);
        ls1 += __shfl_xor_sync(0xffffffffu, ls1, 2);
        lrow0 = lrow0 * cr0 + ls0;
        lrow1 = lrow1 * cr1 + ls1;

        // ---- P -> smem (C-layout to A-layout reshape), tf32 ----
        __syncwarp();   // prior PV fragment loads from Pw are done
#pragma unroll
        for (int n0 = 0; n0 < 8; ++n0) {
            *(uint2*)&Pw[qr * STQ + n0 * 8 + 2 * qc] =
                make_uint2(f2tf32(s[n0][0]), f2tf32(s[n0][1]));
            *(uint2*)&Pw[(qr + 8) * STQ + n0 * 8 + 2 * qc] =
                make_uint2(f2tf32(s[n0][2]), f2tf32(s[n0][3]));
        }
        __syncwarp();

        // ---- O += P @ V ----
#pragma unroll
        for (int k0 = 0; k0 < 8; ++k0) {
            uint32_t aP[4];
            aP[0] = Pw[qr * STQ + k0 * 8 + qc];
            aP[1] = Pw[(qr + 8) * STQ + k0 * 8 + qc];
            aP[2] = Pw[qr * STQ + k0 * 8 + qc + 4];
            aP[3] = Pw[(qr + 8) * STQ + k0 * 8 + qc + 4];
#pragma unroll
            for (int n0 = 0; n0 < 8; ++n0) {
                uint32_t b0 = Vs[(k0 * 8 + qc)     * STV + n0 * 8 + qr];
                uint32_t b1 = Vs[(k0 * 8 + qc + 4) * STV + n0 * 8 + qr];
                mma_tf32(o[n0], aP, b0, b1);
            }
        }
    }

    // ---- epilogue: normalize and store ----
    const float inv0 = 1.f / lrow0, inv1 = 1.f / lrow1;
    const size_t rlo = (size_t)(b * SEQ + q0 + warp * 16 + qr) * INNER + h * HSIZE;
    const size_t rhi = rlo + 8 * INNER;
#pragma unroll
    for (int n0 = 0; n0 < 8; ++n0) {
        *(float2*)(attn + rlo + n0 * 8 + 2 * qc) =
            make_float2(o[n0][0] * inv0, o[n0][1] * inv0);
        *(float2*)(attn + rhi + n0 * 8 + 2 * qc) =
            make_float2(o[n0][2] * inv1, o[n0][3] * inv1);
    }
}

// ---------------------------------------------------------------------------
// Launch
// ---------------------------------------------------------------------------
extern "C" void kernel_launch(void* const* d_in, const int* in_sizes, int n_in,
                              void* d_out, int out_size)
{
    const float* x     = (const float*)d_in[0];
    const float* w_qkv = (const float*)d_in[1];
    const float* b_qkv = (const float*)d_in[2];
    const float* w_out = (const float*)d_in[3];
    const float* b_out = (const float*)d_in[4];
    float* out = (float*)d_out;

    float *qkv_ptr, *attn_ptr;
    cudaGetSymbolAddress((void**)&qkv_ptr, g_qkv);
    cudaGetSymbolAddress((void**)&attn_ptr, g_attn);

    static bool attr_set = false;
    if (!attr_set) {
        cudaFuncSetAttribute(flash_mma_kernel,
                             cudaFuncAttributeMaxDynamicSharedMemorySize,
                             SMEM_BYTES);
        attr_set = true;
    }

    // 1) qkv = x @ w_qkv + b_qkv          [8192,1536]
    {
        dim3 grid(QKVN / 64, MTOT / 128);
        sgemm_bias_kernel<<<grid, 256>>>(x, w_qkv, b_qkv, qkv_ptr, MTOT, QKVN, DIMX);
    }
    // 2) flash attention (tf32 mma) -> g_attn   [8192,512]
    {
        dim3 grid(SEQ / MQ, NHEAD, BATCH);
        flash_mma_kernel<<<grid, 128, SMEM_BYTES>>>(qkv_ptr, attn_ptr);
    }
    // 3) out = attn @ w_out + b_out       [8192,512]
    {
        dim3 grid(DIMX / 64, MTOT / 128);
        sgemm_bias_kernel<<<grid, 256>>>(attn_ptr, w_out, b_out, out, MTOT, DIMX, INNER);
    }
}